// round 1
// baseline (speedup 1.0000x reference)
#include <cuda_runtime.h>
#include <math.h>
#include <math_constants.h>

#define T_   2048
#define DM_  4096
#define H_   16
#define HD_  256
#define RD_  64
#define DFF_ 16384

// ---------------- scratch (device globals: allocation-free) ----------------
__device__ float g_ln [(size_t)T_ * DM_];
__device__ float g_qkv[(size_t)T_ * 3 * DM_];
__device__ float g_ctx[(size_t)T_ * DM_];
__device__ float g_act[(size_t)T_ * DFF_];

// ---------------- LayerNorm ----------------
__global__ void ln_kernel(const float* __restrict__ x,
                          const float* __restrict__ gamma,
                          const float* __restrict__ beta,
                          float* __restrict__ out) {
    int row = blockIdx.x;
    const float4* xr = (const float4*)(x + (size_t)row * DM_);
    float4 v[4];
    float sum = 0.f, sq = 0.f;
#pragma unroll
    for (int i = 0; i < 4; i++) {
        v[i] = xr[threadIdx.x + 256 * i];
        sum += v[i].x + v[i].y + v[i].z + v[i].w;
        sq  += v[i].x * v[i].x + v[i].y * v[i].y + v[i].z * v[i].z + v[i].w * v[i].w;
    }
#pragma unroll
    for (int o = 16; o; o >>= 1) {
        sum += __shfl_xor_sync(0xffffffffu, sum, o);
        sq  += __shfl_xor_sync(0xffffffffu, sq,  o);
    }
    __shared__ float ssum[8], ssq[8];
    int warp = threadIdx.x >> 5, lane = threadIdx.x & 31;
    if (lane == 0) { ssum[warp] = sum; ssq[warp] = sq; }
    __syncthreads();
    sum = 0.f; sq = 0.f;
#pragma unroll
    for (int i = 0; i < 8; i++) { sum += ssum[i]; sq += ssq[i]; }
    float mu  = sum * (1.0f / DM_);
    float var = sq * (1.0f / DM_) - mu * mu;
    float inv = rsqrtf(var + 1e-5f);
    const float4* g4 = (const float4*)gamma;
    const float4* b4 = (const float4*)beta;
    float4* o4 = (float4*)(out + (size_t)row * DM_);
#pragma unroll
    for (int i = 0; i < 4; i++) {
        int idx = threadIdx.x + 256 * i;
        float4 g = g4[idx], b = b4[idx], o;
        o.x = (v[i].x - mu) * inv * g.x + b.x;
        o.y = (v[i].y - mu) * inv * g.y + b.y;
        o.z = (v[i].z - mu) * inv * g.z + b.z;
        o.w = (v[i].w - mu) * inv * g.w + b.w;
        o4[idx] = o;
    }
}

// ---------------- RoPE (GPT-J interleaved) ----------------
__global__ void rope_kernel(float* __restrict__ qkv, const int* __restrict__ positions) {
    int idx = blockIdx.x * blockDim.x + threadIdx.x;   // T*H*2*32 threads
    int i     = idx & 31;
    int which = (idx >> 5) & 1;     // 0 = q, 1 = k
    int h     = (idx >> 6) & 15;
    int t     = idx >> 10;
    float inv = (float)pow(10000.0, -(double)i / 32.0);
    float ang = (float)positions[t] * inv;   // mimic f32 product in reference
    float s, c;
    sincosf(ang, &s, &c);
    float* p = qkv + (size_t)t * (3 * DM_) + (size_t)which * DM_ + h * HD_ + 2 * i;
    float x1 = p[0], x2 = p[1];
    p[0] = x1 * c - x2 * s;
    p[1] = x2 * c + x1 * s;
}

// ---------------- GELU (tanh approx) ----------------
__device__ __forceinline__ float gelu_tanh(float x) {
    float x3 = x * x * x;
    float t  = tanhf(0.7978845608028654f * (x + 0.044715f * x3));
    return 0.5f * x * (1.0f + t);
}

// ---------------- generic fp32 SGEMM, 128x128x8, 8x8/thread ----------------
// EPI: 0 = store, 1 = gelu(acc+bias), 2 = acc+bias+residual, 3 = C += acc
template <int EPI>
__global__ void __launch_bounds__(256)
sgemm_kernel(const float* __restrict__ A, const float* __restrict__ B,
             float* __restrict__ C, int M, int N, int K,
             const float* __restrict__ bias, const float* __restrict__ res) {
    __shared__ float As[8][128];
    __shared__ float Bs[8][128];
    int tid = threadIdx.x;
    int bx = blockIdx.x, by = blockIdx.y;
    int tx = tid & 15, ty = tid >> 4;

    const int arow = tid >> 1, acol = (tid & 1) * 4;
    const int brow = tid >> 5, bcol = (tid & 31) * 4;

    const float* Aptr = A + (size_t)(by * 128 + arow) * K + acol;
    const float* Bptr = B + (size_t)brow * N + bx * 128 + bcol;

    float acc[8][8];
#pragma unroll
    for (int i = 0; i < 8; i++)
#pragma unroll
        for (int j = 0; j < 8; j++) acc[i][j] = 0.f;

    for (int k0 = 0; k0 < K; k0 += 8) {
        float4 a = *(const float4*)(Aptr + k0);
        float4 b = *(const float4*)(Bptr + (size_t)k0 * N);
        As[acol + 0][arow] = a.x;
        As[acol + 1][arow] = a.y;
        As[acol + 2][arow] = a.z;
        As[acol + 3][arow] = a.w;
        *(float4*)&Bs[brow][bcol] = b;
        __syncthreads();
#pragma unroll
        for (int k = 0; k < 8; k++) {
            float ar[8], br[8];
            *(float4*)(ar)     = *(const float4*)&As[k][ty * 8];
            *(float4*)(ar + 4) = *(const float4*)&As[k][ty * 8 + 4];
            *(float4*)(br)     = *(const float4*)&Bs[k][tx * 8];
            *(float4*)(br + 4) = *(const float4*)&Bs[k][tx * 8 + 4];
#pragma unroll
            for (int i = 0; i < 8; i++)
#pragma unroll
                for (int j = 0; j < 8; j++) acc[i][j] += ar[i] * br[j];
        }
        __syncthreads();
    }

#pragma unroll
    for (int i = 0; i < 8; i++) {
        int row = by * 128 + ty * 8 + i;
        float* Crow = C + (size_t)row * N + bx * 128 + tx * 8;
#pragma unroll
        for (int j = 0; j < 8; j++) {
            float v = acc[i][j];
            int col = bx * 128 + tx * 8 + j;
            if (EPI == 1) {
                v = gelu_tanh(v + bias[col]);
            } else if (EPI == 2) {
                v += bias[col] + res[(size_t)row * N + col];
            } else if (EPI == 3) {
                v += Crow[j];
            }
            Crow[j] = v;
        }
    }
}

// ---------------- causal flash attention (fp32) ----------------
// Block: one head, 32 query rows. 256 threads: q = tid>>3 (0..31),
// c = tid&7; thread handles HD elements {c*4 + 32*j + r}, conflict-free float4.
#define BQ 32
#define BK 32
__global__ void __launch_bounds__(256)
attn_kernel(const float* __restrict__ qkv, float* __restrict__ ctx) {
    extern __shared__ float smem[];
    float* Ks = smem;               // [BK][HD]
    float* Vs = smem + BK * HD_;    // [BK][HD]
    int h  = blockIdx.y;
    int qb = blockIdx.x;
    int tid = threadIdx.x;
    int q = tid >> 3;
    int c = tid & 7;
    int tq = qb * BQ + q;

    const float* qrow = qkv + (size_t)tq * (3 * DM_) + h * HD_;
    float qreg[32];
#pragma unroll
    for (int j = 0; j < 8; j++) {
        float4 v = *(const float4*)(qrow + c * 4 + 32 * j);
        qreg[4 * j + 0] = v.x; qreg[4 * j + 1] = v.y;
        qreg[4 * j + 2] = v.z; qreg[4 * j + 3] = v.w;
    }
    float acc[32];
#pragma unroll
    for (int j = 0; j < 32; j++) acc[j] = 0.f;
    float m = -CUDART_INF_F, l = 0.f;
    const float scale = 0.0625f;   // HD^-0.5

    int ntiles = qb + 1;
    for (int kt = 0; kt < ntiles; ++kt) {
        __syncthreads();
        {
            int r  = tid >> 3;
            int cc = tid & 7;
            const float* krow = qkv + (size_t)(kt * BK + r) * (3 * DM_) + DM_ + h * HD_;
            const float* vrow = krow + DM_;
#pragma unroll
            for (int j = 0; j < 8; j++) {
                *(float4*)(Ks + r * HD_ + cc * 4 + 32 * j) = *(const float4*)(krow + cc * 4 + 32 * j);
                *(float4*)(Vs + r * HD_ + cc * 4 + 32 * j) = *(const float4*)(vrow + cc * 4 + 32 * j);
            }
        }
        __syncthreads();

        float s[32];
        float mloc = -CUDART_INF_F;
#pragma unroll 4
        for (int kk = 0; kk < BK; ++kk) {
            const float* kr = Ks + kk * HD_;
            float part = 0.f;
#pragma unroll
            for (int j = 0; j < 8; j++) {
                float4 v = *(const float4*)(kr + c * 4 + 32 * j);
                part += qreg[4 * j] * v.x + qreg[4 * j + 1] * v.y
                      + qreg[4 * j + 2] * v.z + qreg[4 * j + 3] * v.w;
            }
            part += __shfl_xor_sync(0xffffffffu, part, 1);
            part += __shfl_xor_sync(0xffffffffu, part, 2);
            part += __shfl_xor_sync(0xffffffffu, part, 4);
            part *= scale;
            int tk = kt * BK + kk;
            if (tk > tq) part = -CUDART_INF_F;
            s[kk] = part;
            mloc = fmaxf(mloc, part);
        }
        float mnew  = fmaxf(m, mloc);
        float alpha = __expf(m - mnew);
        l *= alpha;
#pragma unroll
        for (int j = 0; j < 32; j++) acc[j] *= alpha;
#pragma unroll 4
        for (int kk = 0; kk < BK; ++kk) {
            float p = __expf(s[kk] - mnew);
            l += p;
            const float* vr = Vs + kk * HD_;
#pragma unroll
            for (int j = 0; j < 8; j++) {
                float4 v = *(const float4*)(vr + c * 4 + 32 * j);
                acc[4 * j + 0] += p * v.x;
                acc[4 * j + 1] += p * v.y;
                acc[4 * j + 2] += p * v.z;
                acc[4 * j + 3] += p * v.w;
            }
        }
        m = mnew;
    }

    float invl = 1.0f / l;
    float* orow = ctx + (size_t)tq * DM_ + h * HD_;
#pragma unroll
    for (int j = 0; j < 8; j++) {
        float4 v = make_float4(acc[4 * j] * invl, acc[4 * j + 1] * invl,
                               acc[4 * j + 2] * invl, acc[4 * j + 3] * invl);
        *(float4*)(orow + c * 4 + 32 * j) = v;
    }
}

// ---------------- launch ----------------
extern "C" void kernel_launch(void* const* d_in, const int* in_sizes, int n_in,
                              void* d_out, int out_size) {
    const int*   positions = (const int*)  d_in[0];
    const float* hidden    = (const float*)d_in[1];
    const float* ln_g      = (const float*)d_in[2];
    const float* ln_b      = (const float*)d_in[3];
    const float* w_qkv     = (const float*)d_in[4];
    const float* w_out     = (const float*)d_in[5];
    const float* w_fc_in   = (const float*)d_in[6];
    const float* b_fc_in   = (const float*)d_in[7];
    const float* w_fc_out  = (const float*)d_in[8];
    const float* b_fc_out  = (const float*)d_in[9];
    float* out = (float*)d_out;

    float *p_ln, *p_qkv, *p_ctx, *p_act;
    cudaGetSymbolAddress((void**)&p_ln,  g_ln);
    cudaGetSymbolAddress((void**)&p_qkv, g_qkv);
    cudaGetSymbolAddress((void**)&p_ctx, g_ctx);
    cudaGetSymbolAddress((void**)&p_act, g_act);

    cudaFuncSetAttribute(attn_kernel, cudaFuncAttributeMaxDynamicSharedMemorySize,
                         2 * BK * HD_ * (int)sizeof(float));

    // 1. LayerNorm
    ln_kernel<<<T_, 256>>>(hidden, ln_g, ln_b, p_ln);

    // 2. QKV GEMM: [2048,4096] @ [4096,12288]
    sgemm_kernel<0><<<dim3(3 * DM_ / 128, T_ / 128), 256>>>(
        p_ln, w_qkv, p_qkv, T_, 3 * DM_, DM_, nullptr, nullptr);

    // 3. RoPE on q and k
    rope_kernel<<<(T_ * H_ * 64) / 256, 256>>>(p_qkv, positions);

    // 4. causal attention -> ctx
    attn_kernel<<<dim3(T_ / BQ, H_), 256, 2 * BK * HD_ * sizeof(float)>>>(p_qkv, p_ctx);

    // 5. MLP fc_in + GELU: [2048,4096] @ [4096,16384]
    sgemm_kernel<1><<<dim3(DFF_ / 128, T_ / 128), 256>>>(
        p_ln, w_fc_in, p_act, T_, DFF_, DM_, b_fc_in, nullptr);

    // 6. MLP fc_out + bias + residual -> out
    sgemm_kernel<2><<<dim3(DM_ / 128, T_ / 128), 256>>>(
        p_act, w_fc_out, out, T_, DM_, DFF_, b_fc_out, hidden);

    // 7. attention out-proj, accumulate into out
    sgemm_kernel<3><<<dim3(DM_ / 128, T_ / 128), 256>>>(
        p_ctx, w_out, out, T_, DM_, DM_, nullptr, nullptr);
}

// round 6
// speedup vs baseline: 1.8646x; 1.8646x over previous
#include <cuda_runtime.h>
#include <cuda_bf16.h>
#include <math.h>
#include <math_constants.h>
#include <cstdint>

#define T_   2048
#define DM_  4096
#define H_   16
#define HD_  256
#define RD_  64
#define DFF_ 16384

// ---------------- scratch (device globals) ----------------
__device__ __nv_bfloat16 g_wqkvT_hi[(size_t)3*DM_*DM_];
__device__ __nv_bfloat16 g_wqkvT_lo[(size_t)3*DM_*DM_];
__device__ __nv_bfloat16 g_woutT_hi[(size_t)DM_*DM_];
__device__ __nv_bfloat16 g_woutT_lo[(size_t)DM_*DM_];
__device__ __nv_bfloat16 g_wfciT_hi[(size_t)DFF_*DM_];
__device__ __nv_bfloat16 g_wfciT_lo[(size_t)DFF_*DM_];
__device__ __nv_bfloat16 g_wfcoT_hi[(size_t)DM_*DFF_];
__device__ __nv_bfloat16 g_wfcoT_lo[(size_t)DM_*DFF_];
__device__ __nv_bfloat16 g_ln_hi[(size_t)T_*DM_];
__device__ __nv_bfloat16 g_ln_lo[(size_t)T_*DM_];
__device__ __nv_bfloat16 g_act_hi[(size_t)T_*DFF_];
__device__ __nv_bfloat16 g_act_lo[(size_t)T_*DFF_];
__device__ __nv_bfloat16 g_ctx_hi[(size_t)T_*DM_];
__device__ __nv_bfloat16 g_ctx_lo[(size_t)T_*DM_];
__device__ float g_qkv[(size_t)T_*3*DM_];

// ---------------- PTX helpers (baseline features only, no 'a'-suffix) --------
__device__ __forceinline__ uint32_t smem_u32(const void* p) {
    uint32_t a;
    asm("{ .reg .u64 t; cvta.to.shared.u64 t, %1; cvt.u32.u64 %0, t; }" : "=r"(a) : "l"(p));
    return a;
}
__device__ __forceinline__ void cp_async16(uint32_t d, const void* g) {
    asm volatile("cp.async.cg.shared.global [%0], [%1], 16;" :: "r"(d), "l"(g));
}
#define CP_COMMIT()  asm volatile("cp.async.commit_group;" ::: "memory")
#define CP_WAIT1()   asm volatile("cp.async.wait_group 1;" ::: "memory")

__device__ __forceinline__ void ldsm4(uint32_t* r, uint32_t addr) {
    asm volatile("ldmatrix.sync.aligned.m8n8.x4.shared.b16 {%0,%1,%2,%3}, [%4];"
                 : "=r"(r[0]), "=r"(r[1]), "=r"(r[2]), "=r"(r[3]) : "r"(addr));
}
__device__ __forceinline__ void mma16816(float* c, const uint32_t* a,
                                         uint32_t b0, uint32_t b1) {
    asm volatile("mma.sync.aligned.m16n8k16.row.col.f32.bf16.bf16.f32 "
                 "{%0,%1,%2,%3}, {%4,%5,%6,%7}, {%8,%9}, {%0,%1,%2,%3};"
                 : "+f"(c[0]), "+f"(c[1]), "+f"(c[2]), "+f"(c[3])
                 : "r"(a[0]), "r"(a[1]), "r"(a[2]), "r"(a[3]), "r"(b0), "r"(b1));
}

__device__ __forceinline__ void split_store(float v, __nv_bfloat16* ph, __nv_bfloat16* pl) {
    __nv_bfloat16 h = __float2bfloat16(v);
    *ph = h;
    *pl = __float2bfloat16(v - __bfloat162float(h));
}

// ---------------- weight transpose + bf16 split ----------------
// W [Krows, Ncols] fp32 row-major -> Wt_hi/lo [Ncols, Krows] bf16 row-major
__global__ void convT_kernel(const float* __restrict__ W,
                             __nv_bfloat16* __restrict__ hi,
                             __nv_bfloat16* __restrict__ lo,
                             int Krows, int Ncols) {
    __shared__ float tile[32][33];
    int n0 = blockIdx.x * 32, k0 = blockIdx.y * 32;
    int tx = threadIdx.x, ty = threadIdx.y;
#pragma unroll
    for (int i = 0; i < 4; i++)
        tile[ty + 8 * i][tx] = W[(size_t)(k0 + ty + 8 * i) * Ncols + n0 + tx];
    __syncthreads();
#pragma unroll
    for (int i = 0; i < 4; i++) {
        int r = ty + 8 * i;
        float v = tile[tx][r];
        size_t o = (size_t)(n0 + r) * Krows + k0 + tx;
        __nv_bfloat16 h = __float2bfloat16(v);
        hi[o] = h;
        lo[o] = __float2bfloat16(v - __bfloat162float(h));
    }
}

// ---------------- LayerNorm -> bf16 hi/lo ----------------
__global__ void ln_kernel(const float* __restrict__ x,
                          const float* __restrict__ gamma,
                          const float* __restrict__ beta,
                          __nv_bfloat16* __restrict__ ohi,
                          __nv_bfloat16* __restrict__ olo) {
    int row = blockIdx.x;
    const float4* xr = (const float4*)(x + (size_t)row * DM_);
    float4 v[4];
    float sum = 0.f, sq = 0.f;
#pragma unroll
    for (int i = 0; i < 4; i++) {
        v[i] = xr[threadIdx.x + 256 * i];
        sum += v[i].x + v[i].y + v[i].z + v[i].w;
        sq  += v[i].x * v[i].x + v[i].y * v[i].y + v[i].z * v[i].z + v[i].w * v[i].w;
    }
#pragma unroll
    for (int o = 16; o; o >>= 1) {
        sum += __shfl_xor_sync(0xffffffffu, sum, o);
        sq  += __shfl_xor_sync(0xffffffffu, sq,  o);
    }
    __shared__ float ssum[8], ssq[8];
    int warp = threadIdx.x >> 5, lane = threadIdx.x & 31;
    if (lane == 0) { ssum[warp] = sum; ssq[warp] = sq; }
    __syncthreads();
    sum = 0.f; sq = 0.f;
#pragma unroll
    for (int i = 0; i < 8; i++) { sum += ssum[i]; sq += ssq[i]; }
    float mu  = sum * (1.0f / DM_);
    float var = sq * (1.0f / DM_) - mu * mu;
    float inv = rsqrtf(var + 1e-5f);
    const float4* g4 = (const float4*)gamma;
    const float4* b4 = (const float4*)beta;
#pragma unroll
    for (int i = 0; i < 4; i++) {
        int idx = threadIdx.x + 256 * i;
        float4 g = g4[idx], b = b4[idx];
        size_t base = (size_t)row * DM_ + idx * 4;
        split_store((v[i].x - mu) * inv * g.x + b.x, ohi + base + 0, olo + base + 0);
        split_store((v[i].y - mu) * inv * g.y + b.y, ohi + base + 1, olo + base + 1);
        split_store((v[i].z - mu) * inv * g.z + b.z, ohi + base + 2, olo + base + 2);
        split_store((v[i].w - mu) * inv * g.w + b.w, ohi + base + 3, olo + base + 3);
    }
}

// ---------------- RoPE (GPT-J interleaved) ----------------
__global__ void rope_kernel(float* __restrict__ qkv, const int* __restrict__ positions) {
    int idx = blockIdx.x * blockDim.x + threadIdx.x;
    int i     = idx & 31;
    int which = (idx >> 5) & 1;
    int h     = (idx >> 6) & 15;
    int t     = idx >> 10;
    float inv = (float)pow(10000.0, -(double)i / 32.0);
    float ang = (float)positions[t] * inv;
    float s, c;
    sincosf(ang, &s, &c);
    float* p = qkv + (size_t)t * (3 * DM_) + (size_t)which * DM_ + h * HD_ + 2 * i;
    float x1 = p[0], x2 = p[1];
    p[0] = x1 * c - x2 * s;
    p[1] = x2 * c + x1 * s;
}

__device__ __forceinline__ float gelu_tanh(float x) {
    float x3 = x * x * x;
    float t  = tanhf(0.7978845608028654f * (x + 0.044715f * x3));
    return 0.5f * x * (1.0f + t);
}

// ---------------- mma.sync split-bf16 GEMM ----------------
// C[M,N] = A[M,K] @ BT[N,K]^T, A/B as bf16 hi/lo splits.
// CTA 128x128, 256 threads, warp tile 64x32 (wm in 0..1, wn in 0..3), KC=32.
// 3-stage cp.async pipeline. SMEM rows padded to 40 bf16 (80B) => conflict-free.
// EPI: 0 store fp32; 1 gelu(v+bias)->Ohi/Olo; 2 v+bias+res->C; 3 C += v
#define KC 32
#define ROWP 40                               // padded row, bf16 elems
#define ARR_BYTES (128 * ROWP * 2)            // 10240
#define STAGE_BYTES (4 * ARR_BYTES)           // 40960: Ahi,Alo,Bhi,Blo
#define NSTAGE 3
#define GEMM_SMEM (NSTAGE * STAGE_BYTES)      // 122880

template <int EPI>
__global__ void __launch_bounds__(256, 1)
mma_gemm(const __nv_bfloat16* __restrict__ Ahi, const __nv_bfloat16* __restrict__ Alo,
         const __nv_bfloat16* __restrict__ Bhi, const __nv_bfloat16* __restrict__ Blo,
         float* __restrict__ C,
         __nv_bfloat16* __restrict__ Ohi, __nv_bfloat16* __restrict__ Olo,
         const float* __restrict__ bias, const float* __restrict__ res,
         int M, int N, int K) {
    extern __shared__ char smem[];
    const uint32_t sb0 = smem_u32(smem);
    int tid = threadIdx.x;
    int lane = tid & 31, wid = tid >> 5;
    int wm = wid >> 2, wn = wid & 3;

    // supertile rasterization (groups of 8 N-blocks) for L2 reuse
    int nbn = N / 128, nbm = M / 128;
    const int SWT = 8;
    int per = SWT * nbm;
    int ggrp = blockIdx.x / per, rem = blockIdx.x - ggrp * per;
    int bn0 = ggrp * SWT;
    int w = nbn - bn0; if (w > SWT) w = SWT;
    int bn = bn0 + rem % w;
    int bm = rem / w;

    float acc[4][4][4];
#pragma unroll
    for (int i = 0; i < 4; i++)
#pragma unroll
        for (int j = 0; j < 4; j++)
#pragma unroll
            for (int q = 0; q < 4; q++) acc[i][j][q] = 0.f;

    auto load_stage = [&](int s, int k0) {
        uint32_t sb = sb0 + s * STAGE_BYTES;
#pragma unroll
        for (int arr = 0; arr < 4; arr++) {
            const __nv_bfloat16* g = (arr == 0) ? Ahi : (arr == 1) ? Alo
                                   : (arr == 2) ? Bhi : Blo;
            size_t rb = (arr < 2) ? (size_t)bm * 128 : (size_t)bn * 128;
#pragma unroll
            for (int j = 0; j < 2; j++) {
                int i = tid + 256 * j;          // 0..511
                int row = i >> 2, c = i & 3;    // 4 x 16B chunks per 64B row
                cp_async16(sb + arr * ARR_BYTES + row * (ROWP * 2) + c * 16,
                           g + (rb + row) * (size_t)K + k0 + c * 8);
            }
        }
    };

    load_stage(0, 0); CP_COMMIT();
    load_stage(1, KC); CP_COMMIT();

    // per-warp ldmatrix base addresses (stage offset added in loop)
    uint32_t aBase = sb0 + (wm * 64 + (lane & 15)) * (ROWP * 2) + ((lane >> 4) * 8) * 2;
    uint32_t bBase = sb0 + 2 * ARR_BYTES + (wn * 32 + (lane & 15)) * (ROWP * 2) + ((lane >> 4) * 8) * 2;

    int nk = K / KC;
    for (int kc = 0; kc < nk; kc++) {
        CP_WAIT1();
        __syncthreads();
        uint32_t so = (kc % NSTAGE) * STAGE_BYTES;
#pragma unroll
        for (int ks = 0; ks < 2; ks++) {
            uint32_t bh[8], bl[8];
            ldsm4(bh,     bBase + so + ks * 32);
            ldsm4(bh + 4, bBase + so + 16 * (ROWP * 2) + ks * 32);
            ldsm4(bl,     bBase + so + ARR_BYTES + ks * 32);
            ldsm4(bl + 4, bBase + so + ARR_BYTES + 16 * (ROWP * 2) + ks * 32);
#pragma unroll
            for (int i = 0; i < 4; i++) {
                uint32_t ah[4], al[4];
                ldsm4(ah, aBase + so + i * 16 * (ROWP * 2) + ks * 32);
                ldsm4(al, aBase + so + ARR_BYTES + i * 16 * (ROWP * 2) + ks * 32);
#pragma unroll
                for (int j = 0; j < 4; j++) {
                    int j2 = j >> 1, ss = j & 1;
                    uint32_t b0h = bh[j2 * 4 + ss], b1h = bh[j2 * 4 + ss + 2];
                    uint32_t b0l = bl[j2 * 4 + ss], b1l = bl[j2 * 4 + ss + 2];
                    mma16816(acc[i][j], ah, b0h, b1h);
                    mma16816(acc[i][j], ah, b0l, b1l);
                    mma16816(acc[i][j], al, b0h, b1h);
                }
            }
        }
        __syncthreads();
        if (kc + 2 < nk) load_stage((kc + 2) % NSTAGE, (kc + 2) * KC);
        CP_COMMIT();
    }

    // epilogue: acc thread mapping: g=lane>>2, cc=lane&3
    int gq = lane >> 2, cc = lane & 3;
#pragma unroll
    for (int i = 0; i < 4; i++) {
#pragma unroll
        for (int j = 0; j < 4; j++) {
            int row = bm * 128 + wm * 64 + i * 16 + gq;
            int col = bn * 128 + wn * 32 + j * 8 + 2 * cc;
            float* a4 = acc[i][j];
#pragma unroll
            for (int half = 0; half < 2; half++) {
                int r = row + 8 * half;
                float v0 = a4[2 * half], v1 = a4[2 * half + 1];
                size_t base = (size_t)r * N + col;
                if (EPI == 0) {
                    *(float2*)(C + base) = make_float2(v0, v1);
                } else if (EPI == 1) {
                    float g0 = gelu_tanh(v0 + bias[col]);
                    float g1 = gelu_tanh(v1 + bias[col + 1]);
                    split_store(g0, Ohi + base, Olo + base);
                    split_store(g1, Ohi + base + 1, Olo + base + 1);
                } else if (EPI == 2) {
                    float2 rr = *(const float2*)(res + base);
                    *(float2*)(C + base) = make_float2(v0 + bias[col] + rr.x,
                                                       v1 + bias[col + 1] + rr.y);
                } else {
                    float2 cur = *(float2*)(C + base);
                    *(float2*)(C + base) = make_float2(cur.x + v0, cur.y + v1);
                }
            }
        }
    }
}

// ---------------- causal flash attention (fp32), ctx -> bf16 hi/lo ----------------
#define BQ 32
#define BK 32
__global__ void __launch_bounds__(256)
attn_kernel(const float* __restrict__ qkv,
            __nv_bfloat16* __restrict__ chi, __nv_bfloat16* __restrict__ clo) {
    extern __shared__ float smemf[];
    float* Ks = smemf;
    float* Vs = smemf + BK * HD_;
    int h  = blockIdx.y;
    int qb = blockIdx.x;
    int tid = threadIdx.x;
    int q = tid >> 3;
    int c = tid & 7;
    int tq = qb * BQ + q;

    const float* qrow = qkv + (size_t)tq * (3 * DM_) + h * HD_;
    float qreg[32];
#pragma unroll
    for (int j = 0; j < 8; j++) {
        float4 v = *(const float4*)(qrow + c * 4 + 32 * j);
        qreg[4 * j + 0] = v.x; qreg[4 * j + 1] = v.y;
        qreg[4 * j + 2] = v.z; qreg[4 * j + 3] = v.w;
    }
    float acc[32];
#pragma unroll
    for (int j = 0; j < 32; j++) acc[j] = 0.f;
    float m = -CUDART_INF_F, l = 0.f;
    const float scale = 0.0625f;

    int ntiles = qb + 1;
    for (int kt = 0; kt < ntiles; ++kt) {
        __syncthreads();
        {
            int r  = tid >> 3;
            int cc = tid & 7;
            const float* krow = qkv + (size_t)(kt * BK + r) * (3 * DM_) + DM_ + h * HD_;
            const float* vrow = krow + DM_;
#pragma unroll
            for (int j = 0; j < 8; j++) {
                *(float4*)(Ks + r * HD_ + cc * 4 + 32 * j) = *(const float4*)(krow + cc * 4 + 32 * j);
                *(float4*)(Vs + r * HD_ + cc * 4 + 32 * j) = *(const float4*)(vrow + cc * 4 + 32 * j);
            }
        }
        __syncthreads();

        float s[32];
        float mloc = -CUDART_INF_F;
#pragma unroll 4
        for (int kk = 0; kk < BK; ++kk) {
            const float* kr = Ks + kk * HD_;
            float part = 0.f;
#pragma unroll
            for (int j = 0; j < 8; j++) {
                float4 v = *(const float4*)(kr + c * 4 + 32 * j);
                part += qreg[4 * j] * v.x + qreg[4 * j + 1] * v.y
                      + qreg[4 * j + 2] * v.z + qreg[4 * j + 3] * v.w;
            }
            part += __shfl_xor_sync(0xffffffffu, part, 1);
            part += __shfl_xor_sync(0xffffffffu, part, 2);
            part += __shfl_xor_sync(0xffffffffu, part, 4);
            part *= scale;
            int tk = kt * BK + kk;
            if (tk > tq) part = -CUDART_INF_F;
            s[kk] = part;
            mloc = fmaxf(mloc, part);
        }
        float mnew  = fmaxf(m, mloc);
        float alpha = __expf(m - mnew);
        l *= alpha;
#pragma unroll
        for (int j = 0; j < 32; j++) acc[j] *= alpha;
#pragma unroll 4
        for (int kk = 0; kk < BK; ++kk) {
            float p = __expf(s[kk] - mnew);
            l += p;
            const float* vr = Vs + kk * HD_;
#pragma unroll
            for (int j = 0; j < 8; j++) {
                float4 v = *(const float4*)(vr + c * 4 + 32 * j);
                acc[4 * j + 0] += p * v.x;
                acc[4 * j + 1] += p * v.y;
                acc[4 * j + 2] += p * v.z;
                acc[4 * j + 3] += p * v.w;
            }
        }
        m = mnew;
    }

    float invl = 1.0f / l;
    size_t obase = (size_t)tq * DM_ + h * HD_;
#pragma unroll
    for (int j = 0; j < 8; j++) {
#pragma unroll
        for (int ii = 0; ii < 4; ii++) {
            float v = acc[4 * j + ii] * invl;
            size_t o = obase + c * 4 + 32 * j + ii;
            split_store(v, chi + o, clo + o);
        }
    }
}

// ---------------- launch ----------------
extern "C" void kernel_launch(void* const* d_in, const int* in_sizes, int n_in,
                              void* d_out, int out_size) {
    const int*   positions = (const int*)  d_in[0];
    const float* hidden    = (const float*)d_in[1];
    const float* ln_g      = (const float*)d_in[2];
    const float* ln_b      = (const float*)d_in[3];
    const float* w_qkv     = (const float*)d_in[4];
    const float* w_out     = (const float*)d_in[5];
    const float* w_fc_in   = (const float*)d_in[6];
    const float* b_fc_in   = (const float*)d_in[7];
    const float* w_fc_out  = (const float*)d_in[8];
    const float* b_fc_out  = (const float*)d_in[9];
    float* out = (float*)d_out;

    __nv_bfloat16 *wqh, *wql, *woh, *wol, *wih, *wil, *wfh, *wfl;
    __nv_bfloat16 *lnh, *lnl, *ach, *acl, *cxh, *cxl;
    float *p_qkv;
    cudaGetSymbolAddress((void**)&wqh, g_wqkvT_hi);  cudaGetSymbolAddress((void**)&wql, g_wqkvT_lo);
    cudaGetSymbolAddress((void**)&woh, g_woutT_hi);  cudaGetSymbolAddress((void**)&wol, g_woutT_lo);
    cudaGetSymbolAddress((void**)&wih, g_wfciT_hi);  cudaGetSymbolAddress((void**)&wil, g_wfciT_lo);
    cudaGetSymbolAddress((void**)&wfh, g_wfcoT_hi);  cudaGetSymbolAddress((void**)&wfl, g_wfcoT_lo);
    cudaGetSymbolAddress((void**)&lnh, g_ln_hi);     cudaGetSymbolAddress((void**)&lnl, g_ln_lo);
    cudaGetSymbolAddress((void**)&ach, g_act_hi);    cudaGetSymbolAddress((void**)&acl, g_act_lo);
    cudaGetSymbolAddress((void**)&cxh, g_ctx_hi);    cudaGetSymbolAddress((void**)&cxl, g_ctx_lo);
    cudaGetSymbolAddress((void**)&p_qkv, g_qkv);

    cudaFuncSetAttribute(mma_gemm<0>, cudaFuncAttributeMaxDynamicSharedMemorySize, GEMM_SMEM);
    cudaFuncSetAttribute(mma_gemm<1>, cudaFuncAttributeMaxDynamicSharedMemorySize, GEMM_SMEM);
    cudaFuncSetAttribute(mma_gemm<2>, cudaFuncAttributeMaxDynamicSharedMemorySize, GEMM_SMEM);
    cudaFuncSetAttribute(mma_gemm<3>, cudaFuncAttributeMaxDynamicSharedMemorySize, GEMM_SMEM);
    cudaFuncSetAttribute(attn_kernel, cudaFuncAttributeMaxDynamicSharedMemorySize,
                         2 * BK * HD_ * (int)sizeof(float));

    dim3 cb(32, 8);
    convT_kernel<<<dim3(3 * DM_ / 32, DM_ / 32), cb>>>(w_qkv,   wqh, wql, DM_,  3 * DM_);
    convT_kernel<<<dim3(DM_ / 32,     DM_ / 32), cb>>>(w_out,   woh, wol, DM_,  DM_);
    convT_kernel<<<dim3(DFF_ / 32,    DM_ / 32), cb>>>(w_fc_in, wih, wil, DM_,  DFF_);
    convT_kernel<<<dim3(DM_ / 32,    DFF_ / 32), cb>>>(w_fc_out,wfh, wfl, DFF_, DM_);

    ln_kernel<<<T_, 256>>>(hidden, ln_g, ln_b, lnh, lnl);

    // QKV GEMM -> fp32 qkv
    mma_gemm<0><<<(T_ / 128) * (3 * DM_ / 128), 256, GEMM_SMEM>>>(
        lnh, lnl, wqh, wql, p_qkv, nullptr, nullptr, nullptr, nullptr,
        T_, 3 * DM_, DM_);

    rope_kernel<<<(T_ * H_ * 64) / 256, 256>>>(p_qkv, positions);

    attn_kernel<<<dim3(T_ / BQ, H_), 256, 2 * BK * HD_ * sizeof(float)>>>(p_qkv, cxh, cxl);

    // fc_in + gelu -> act hi/lo
    mma_gemm<1><<<(T_ / 128) * (DFF_ / 128), 256, GEMM_SMEM>>>(
        lnh, lnl, wih, wil, nullptr, ach, acl, b_fc_in, nullptr,
        T_, DFF_, DM_);

    // fc_out + bias + residual -> out
    mma_gemm<2><<<(T_ / 128) * (DM_ / 128), 256, GEMM_SMEM>>>(
        ach, acl, wfh, wfl, out, nullptr, nullptr, b_fc_out, hidden,
        T_, DM_, DFF_);

    // attention out-proj, accumulate into out
    mma_gemm<3><<<(T_ / 128) * (DM_ / 128), 256, GEMM_SMEM>>>(
        cxh, cxl, woh, wol, out, nullptr, nullptr, nullptr, nullptr,
        T_, DM_, DM_);
}